// round 12
// baseline (speedup 1.0000x reference)
#include <cuda_runtime.h>

#define B_ 64
#define T_ 512
#define DIN 256
#define H_ 1024
#define DOUT 256
#define NCTA 128
#define NT 256

constexpr int KTX = 8;    // x k-groups (32 k each)
constexpr int KTH = 32;   // h k-groups
constexpr float SW0 = 256.f, SWH = 512.f, SX = 16.f, SH = 128.f;
constexpr float SC0 = 1.f / (256.f * 16.f);
constexpr float SCH = 1.f / (512.f * 128.f);

constexpr size_t W0SZ = (size_t)64 * 3 * KTX * 64;
constexpr size_t WHSZ = (size_t)64 * 3 * KTH * 64;

__device__ uint4 g_wA[W0SZ + 3 * WHSZ];              // int8 limb frag tables
__device__ unsigned g_xw[(size_t)T_ * KTX * 64 * 16];// x limbs [t][kg][b][16w]
__device__ unsigned g_h0w[2][KTH * 64 * 16], g_h1w[2][KTH * 64 * 16];
__device__ float g_h0f[2][B_ * H_], g_h1f[2][B_ * H_];
__device__ float g_pL0[NCTA * 4096], g_pL1[NCTA * 4096];
__device__ volatile unsigned g_fL0[NCTA], g_fL1[NCTA];
__device__ unsigned g_bar, g_done;

__device__ __forceinline__ float sigf(float x) {
    return __fdividef(1.0f, 1.0f + __expf(-x));
}
__device__ __forceinline__ float tanh_(float x) {
    return __fdividef(2.0f, 1.0f + __expf(-2.0f * x)) - 1.0f;
}
__device__ __forceinline__ int qb(float w, float s, int hl) {
    float t = w * s;
    float l1 = fminf(127.f, fmaxf(-127.f, rintf(t)));
    if (!hl) return (int)l1;
    float l2 = fminf(127.f, fmaxf(-127.f, rintf((t - l1) * 128.f)));
    return (int)l2;
}
__device__ __forceinline__ unsigned pack4(int a, int b, int c, int d) {
    return (a & 0xFF) | ((b & 0xFF) << 8) | ((c & 0xFF) << 16) | ((d & 0xFF) << 24);
}
__device__ __forceinline__ void mma_s8(int (&d)[4], const uint4 a,
                                       unsigned b0, unsigned b1) {
    asm volatile(
        "mma.sync.aligned.m16n8k32.row.col.s32.s8.s8.s32 "
        "{%0,%1,%2,%3},{%4,%5,%6,%7},{%8,%9},{%0,%1,%2,%3};"
        : "+r"(d[0]), "+r"(d[1]), "+r"(d[2]), "+r"(d[3])
        : "r"(a.x), "r"(a.y), "r"(a.z), "r"(a.w), "r"(b0), "r"(b1));
}
__device__ __forceinline__ void grid_sync(unsigned gen) {
    __syncthreads();
    if (threadIdx.x == 0) {
        __threadfence();
        atomicAdd(&g_bar, 1u);
        while (*((volatile unsigned*)&g_bar) < gen * NCTA) { }
        __threadfence();
    }
    __syncthreads();
}

// One GEMM segment: 3 gates x 2 n8 x CNT kg32. P += A1*B1; Q += A1*B2 + A2*B1.
template<int KT, int CNT>
__device__ __forceinline__ void seg_run(
    const uint4* __restrict__ fA,      // + jt*3*KT*64 + lane
    const unsigned* __restrict__ bw,   // act word base
    int kgs, int nb, int lane,
    int (&P)[3][2][4], int (&Q)[3][2][4])
{
    const unsigned loff = (unsigned)((lane >> 2) * 16 + (lane & 3));
#pragma unroll
    for (int k = 0; k < CNT; ++k) {
        const int kg = kgs + k;
        uint4 A1[3], A2[3];
#pragma unroll
        for (int g = 0; g < 3; ++g) {
            A1[g] = fA[(g * KT + kg) * 64];
            A2[g] = fA[(g * KT + kg) * 64 + 32];
        }
#pragma unroll
        for (int p = 0; p < 2; ++p) {
            const unsigned* r = bw + (size_t)(kg * 64 + nb + p * 8) * 16 + loff;
            unsigned b10 = r[0], b11 = r[4], b20 = r[8], b21 = r[12];
#pragma unroll
            for (int g = 0; g < 3; ++g) {
                mma_s8(P[g][p], A1[g], b10, b11);
                mma_s8(Q[g][p], A1[g], b20, b21);
                mma_s8(Q[g][p], A2[g], b10, b11);
            }
        }
    }
}

__device__ __forceinline__ void foldPQ(
    int (&P)[3][2][4], int (&Q)[3][2][4], float sc,
    float (&fR)[2][4], float (&fZ)[2][4], float (&fN)[2][4])
{
#pragma unroll
    for (int p = 0; p < 2; ++p)
#pragma unroll
        for (int e = 0; e < 4; ++e) {
            fR[p][e] += ((float)P[0][p][e] + (float)Q[0][p][e] * 0.0078125f) * sc;
            fZ[p][e] += ((float)P[1][p][e] + (float)Q[1][p][e] * 0.0078125f) * sc;
            fN[p][e] += ((float)P[2][p][e] + (float)Q[2][p][e] * 0.0078125f) * sc;
            P[0][p][e] = 0; P[1][p][e] = 0; P[2][p][e] = 0;
            Q[0][p][e] = 0; Q[1][p][e] = 0; Q[2][p][e] = 0;
        }
}

// 2-way ksub reduce via SMEM + publish [q4][j16][b64].
__device__ __forceinline__ void reduce_pub(
    float (&fR)[2][4], float (&fZ)[2][4], float (&fNi)[2][4], float (&fNh)[2][4],
    float* __restrict__ pOut, float* rbuf, int nsub, int ksub, int lane)
{
    if (ksub) {
        float* dst = rbuf + (nsub * 32) * 32 + lane;
#pragma unroll
        for (int i = 0; i < 8; ++i) {
            dst[(0 + i) * 32]  = fR[i >> 2][i & 3];
            dst[(8 + i) * 32]  = fZ[i >> 2][i & 3];
            dst[(16 + i) * 32] = fNi[i >> 2][i & 3];
            dst[(24 + i) * 32] = fNh[i >> 2][i & 3];
        }
    }
    __syncthreads();
    if (ksub == 0) {
        const float* src = rbuf + (nsub * 32) * 32 + lane;
#pragma unroll
        for (int q = 0; q < 4; ++q)
#pragma unroll
            for (int i = 0; i < 8; ++i) {
                float v = (q == 0 ? fR[i >> 2][i & 3] : q == 1 ? fZ[i >> 2][i & 3]
                         : q == 2 ? fNi[i >> 2][i & 3] : fNh[i >> 2][i & 3]);
                v += src[(q * 8 + i) * 32];
                int jl = (lane >> 2) + 8 * ((i & 3) >> 1);
                int b  = nsub * 16 + (i >> 2) * 8 + 2 * (lane & 3) + (i & 1);
                pOut[q * 1024 + jl * 64 + b] = v;
            }
    }
    __syncthreads();
}

__device__ __forceinline__ void gatepass(
    const float* __restrict__ pOwn, const float* __restrict__ pPar,
    const float* bsv,
    const float* __restrict__ hpf, float* __restrict__ hnf,
    unsigned* __restrict__ hw,
    int jt, int ks, int tid)
{
    const int b = tid & 63, jl2 = tid >> 6;
    unsigned char* h8 = (unsigned char*)hw;
#pragma unroll
    for (int jj = 0; jj < 2; ++jj) {
        int jl = 8 * ks + jl2 * 2 + jj;
        int j  = jt * 16 + jl;
        int o  = jl * 64 + b;
        float r  = pOwn[o]        + pPar[o];
        float z  = pOwn[1024 + o] + pPar[1024 + o];
        float ni = pOwn[2048 + o] + pPar[2048 + o];
        float nh = pOwn[3072 + o] + pPar[3072 + o];
        r = sigf(r + bsv[jj * 4 + 0]);
        z = sigf(z + bsv[jj * 4 + 1]);
        float n = tanh_(ni + bsv[jj * 4 + 2] + r * (nh + bsv[jj * 4 + 3]));
        float hp = hpf[b * H_ + j];
        float h  = n + z * (hp - n);
        hnf[b * H_ + j] = h;
        float t1 = h * SH;
        float l1 = fminf(127.f, fmaxf(-127.f, rintf(t1)));
        float l2 = fminf(127.f, fmaxf(-127.f, rintf((t1 - l1) * 128.f)));
        size_t row = ((size_t)(j >> 5) * 64 + b) * 64;
        h8[row + (j & 31)]      = (unsigned char)(int)l1;
        h8[row + 32 + (j & 31)] = (unsigned char)(int)l2;
    }
}

__global__ void __launch_bounds__(NT, 1) gru_i8(
    const float* __restrict__ x,
    const float* __restrict__ Wi0, const float* __restrict__ Wh0,
    const float* __restrict__ bi0, const float* __restrict__ bh0,
    const float* __restrict__ Wi1, const float* __restrict__ Wh1,
    const float* __restrict__ bi1, const float* __restrict__ bh1,
    const float* __restrict__ Wo,  const float* __restrict__ bo,
    float* __restrict__ out)
{
    __shared__ float rbuf[4 * 32 * 32];   // 16 KB ksub-reduce buffer

    const int tid  = threadIdx.x, lane = tid & 31, warp = tid >> 5;
    const int cta  = blockIdx.x;
    const int jt   = cta >> 1;       // j-tile (16 gate rows)
    const int ks   = cta & 1;        // k-half
    const int nsub = warp & 3;       // batch quarter (16)
    const int ksub = warp >> 2;      // k-half of the CTA's half
    const int nb   = nsub * 16;

    // ---- prep: x -> int8 limb words ----
    for (size_t i = (size_t)cta * NT + tid; i < (size_t)T_ * KTX * 64 * 16;
         i += (size_t)NCTA * NT) {
        int wd = (int)(i & 15);
        int b  = (int)((i >> 4) & 63);
        int kg = (int)((i >> 10) & 7);
        int t  = (int)(i >> 13);
        int hl = wd >> 3, k0 = kg * 32 + (wd & 7) * 4;
        const float* xp = x + ((size_t)b * T_ + t) * DIN + k0;
        g_xw[i] = pack4(qb(xp[0], SX, hl), qb(xp[1], SX, hl),
                        qb(xp[2], SX, hl), qb(xp[3], SX, hl));
    }
    // ---- zero initial state (buffer 1 read first) ----
    for (int i = cta * NT + tid; i < KTH * 64 * 16; i += NCTA * NT) {
        g_h0w[1][i] = 0u; g_h1w[1][i] = 0u;
    }
    for (int i = cta * NT + tid; i < B_ * H_; i += NCTA * NT) {
        g_h0f[1][i] = 0.f; g_h1f[1][i] = 0.f;
    }
    // ---- weights -> int8 limb fragment tables ----
    {
        const float* Wp[4] = { Wi0, Wh0, Wi1, Wh1 };
        const int    Kp[4] = { DIN, H_, H_, H_ };
        const int    KTp[4] = { KTX, KTH, KTH, KTH };
        const float  Sp[4] = { SW0, SWH, SWH, SWH };
        const size_t Fp[4] = { 0, W0SZ, W0SZ + WHSZ, W0SZ + 2 * WHSZ };
        for (int p = 0; p < 4; ++p) {
            const int K = Kp[p], KT = KTp[p];
            const float s = Sp[p];
            const float* W = Wp[p];
            const size_t total = (size_t)64 * 3 * KT * 64;
            for (size_t i = (size_t)cta * NT + tid; i < total;
                 i += (size_t)NCTA * NT) {
                int l = (int)(i & 31), hl = (int)((i >> 5) & 1);
                size_t rest = i >> 6;
                int kg = (int)(rest % KT);
                int g  = (int)((rest / KT) % 3);
                int jtt = (int)(rest / (KT * 3));
                int r0 = g * H_ + jtt * 16 + (l >> 2), r1 = r0 + 8;
                int kb = kg * 32 + (l & 3) * 4;
                const float* p0 = W + (size_t)r0 * K + kb;
                const float* p1 = W + (size_t)r1 * K + kb;
                uint4 v;
                v.x = pack4(qb(p0[0], s, hl), qb(p0[1], s, hl),
                            qb(p0[2], s, hl), qb(p0[3], s, hl));
                v.y = pack4(qb(p1[0], s, hl), qb(p1[1], s, hl),
                            qb(p1[2], s, hl), qb(p1[3], s, hl));
                v.z = pack4(qb(p0[16], s, hl), qb(p0[17], s, hl),
                            qb(p0[18], s, hl), qb(p0[19], s, hl));
                v.w = pack4(qb(p1[16], s, hl), qb(p1[17], s, hl),
                            qb(p1[18], s, hl), qb(p1[19], s, hl));
                g_wA[Fp[p] + ((size_t)(jtt * 3 + g) * KT + kg) * 64 + hl * 32 + l] = v;
            }
        }
    }
    // ---- gate-pass biases ----
    float bs0v[8], bs1v[8];
    {
        const int jl2 = tid >> 6;
#pragma unroll
        for (int jj = 0; jj < 2; ++jj) {
            int j = jt * 16 + 8 * ks + jl2 * 2 + jj;
            bs0v[jj * 4 + 0] = bi0[j] + bh0[j];
            bs0v[jj * 4 + 1] = bi0[H_ + j] + bh0[H_ + j];
            bs0v[jj * 4 + 2] = bi0[2 * H_ + j];
            bs0v[jj * 4 + 3] = bh0[2 * H_ + j];
            bs1v[jj * 4 + 0] = bi1[j] + bh1[j];
            bs1v[jj * 4 + 1] = bi1[H_ + j] + bh1[H_ + j];
            bs1v[jj * 4 + 2] = bi1[2 * H_ + j];
            bs1v[jj * 4 + 3] = bh1[2 * H_ + j];
        }
    }

    const uint4* fWi0 = g_wA + (size_t)jt * 3 * KTX * 64 + lane;
    const uint4* fWh0 = g_wA + W0SZ + (size_t)jt * 3 * KTH * 64 + lane;
    const uint4* fWi1 = g_wA + W0SZ + WHSZ + (size_t)jt * 3 * KTH * 64 + lane;
    const uint4* fWh1 = g_wA + W0SZ + 2 * WHSZ + (size_t)jt * 3 * KTH * 64 + lane;
    const int kgsX = ks * 4 + ksub * 2;    // x GEMM: 2 kg32 per warp
    const int kgsH = ks * 16 + ksub * 8;   // h GEMMs: 8 kg32 per warp

    float* pOwn0 = g_pL0 + cta * 4096;
    float* pOwn1 = g_pL1 + cta * 4096;
    const float* pPar0 = g_pL0 + (cta ^ 1) * 4096;
    const float* pPar1 = g_pL1 + (cta ^ 1) * 4096;

    unsigned gen = 0;
    grid_sync(++gen);   // prep visible

    for (int p = 0; p <= T_; ++p) {
        const int rb0 = (p + 1) & 1;
        // ---- layer0(t=p) ----
        if (p < T_) {
            int P[3][2][4] = {}, Q[3][2][4] = {};
            float fR[2][4] = {}, fZ[2][4] = {}, fNi[2][4] = {}, fNh[2][4] = {};
            seg_run<KTX, 2>(fWi0, g_xw + (size_t)p * 8192, kgsX, nb, lane, P, Q);
            foldPQ(P, Q, SC0, fR, fZ, fNi);
            seg_run<KTH, 8>(fWh0, g_h0w[rb0], kgsH, nb, lane, P, Q);
            foldPQ(P, Q, SCH, fR, fZ, fNh);
            reduce_pub(fR, fZ, fNi, fNh, pOwn0, rbuf, nsub, ksub, lane);
        }
        __syncthreads();
        if (tid == 0 && p < T_) { __threadfence(); g_fL0[cta] = p + 1; }
        // ---- layer1(t=p-1) ----
        if (p > 0) {
            int P[3][2][4] = {}, Q[3][2][4] = {};
            float fR[2][4] = {}, fZ[2][4] = {}, fNi[2][4] = {}, fNh[2][4] = {};
            seg_run<KTH, 8>(fWi1, g_h0w[rb0], kgsH, nb, lane, P, Q);
            foldPQ(P, Q, SCH, fR, fZ, fNi);
            seg_run<KTH, 8>(fWh1, g_h1w[p & 1], kgsH, nb, lane, P, Q);
            foldPQ(P, Q, SCH, fR, fZ, fNh);
            reduce_pub(fR, fZ, fNi, fNh, pOwn1, rbuf, nsub, ksub, lane);
        }
        __syncthreads();
        if (tid == 0) {
            if (p > 0) { __threadfence(); g_fL1[cta] = p; }
            if (p < T_) while (g_fL0[cta ^ 1] < (unsigned)(p + 1)) { }
            if (p > 0)  while (g_fL1[cta ^ 1] < (unsigned)p) { }
            __threadfence();
        }
        __syncthreads();
        // ---- gate passes ----
        if (p < T_)
            gatepass(pOwn0, pPar0, bs0v, g_h0f[rb0], g_h0f[p & 1],
                     g_h0w[p & 1], jt, ks, tid);
        if (p > 0)
            gatepass(pOwn1, pPar1, bs1v, g_h1f[p & 1], g_h1f[(p + 1) & 1],
                     g_h1w[(p + 1) & 1], jt, ks, tid);
        grid_sync(++gen);
    }

    // ---- output projection: h1(511) in g_h1f[1] ----
    if (tid < 128) {
        const int o = cta * 2 + (tid >> 6);
        const int b = tid & 63;
        const float* w  = Wo + (size_t)o * H_;
        const float* hv = g_h1f[1] + (size_t)b * H_;
        float acc = 0.f;
#pragma unroll 4
        for (int k = 0; k < H_; k += 4) {
            float4 wv = *(const float4*)(w + k);
            float4 h4 = *(const float4*)(hv + k);
            acc += wv.x * h4.x + wv.y * h4.y + wv.z * h4.z + wv.w * h4.w;
        }
        out[(size_t)b * DOUT + o] = acc + bo[o];
    }

    // ---- reset persistent counters for next replay ----
    __syncthreads();
    if (tid == 0) {
        unsigned old = atomicAdd(&g_done, 1u);
        if (old == NCTA - 1u) {
            for (int i = 0; i < NCTA; ++i) { g_fL0[i] = 0u; g_fL1[i] = 0u; }
            g_bar = 0u;
            g_done = 0u;
            __threadfence();
        }
    }
}

extern "C" void kernel_launch(void* const* d_in, const int* in_sizes, int n_in,
                              void* d_out, int out_size)
{
    gru_i8<<<NCTA, NT>>>(
        (const float*)d_in[0], (const float*)d_in[1], (const float*)d_in[2],
        (const float*)d_in[3], (const float*)d_in[4], (const float*)d_in[5],
        (const float*)d_in[6], (const float*)d_in[7], (const float*)d_in[8],
        (const float*)d_in[9], (const float*)d_in[10], (float*)d_out);
}

// round 13
// speedup vs baseline: 1.9505x; 1.9505x over previous
#include <cuda_runtime.h>
#include <cuda_bf16.h>

#define B_   64
#define T_   512
#define DIN  256
#define H_   1024
#define DOUT 256
#define NCTA 256
#define NT   256

constexpr int KT0 = 16;
constexpr int KTH = 64;
constexpr size_t FSZ0 = (size_t)64 * 3 * KT0 * 64;
constexpr size_t FSZH = (size_t)64 * 3 * KTH * 64;
constexpr size_t FB0 = 0, FB1 = FSZ0, FB2 = FSZ0 + FSZH, FB3 = FSZ0 + 2 * FSZH;

__device__ uint4 g_wA[FSZ0 + 3 * FSZH];           // fragment-direct weights hi/lo
__device__ float g_h0f[2][B_ * H_], g_h1f[2][B_ * H_];
__device__ uint4 g_h0x[2][KTH * B_ * 4];          // frag-ordered h [kg][b][qq]
__device__ uint4 g_h1x[2][KTH * B_ * 4];
__device__ uint4 g_xx[(size_t)T_ * KT0 * B_ * 4];
__device__ float g_p0[(size_t)NCTA * 2048];       // partials [cta][q4][jl16][b32]
__device__ float g_p1[(size_t)NCTA * 2048];
__device__ volatile unsigned g_f0[NCTA], g_f1[NCTA];
__device__ unsigned g_bar, g_done;

__device__ __forceinline__ unsigned short bfbits(float v) {
    __nv_bfloat16 b = __float2bfloat16_rn(v);
    return *reinterpret_cast<unsigned short*>(&b);
}
__device__ __forceinline__ float bf2f(unsigned short u) {
    __nv_bfloat16 b = *reinterpret_cast<__nv_bfloat16*>(&u);
    return __bfloat162float(b);
}
__device__ __forceinline__ unsigned pk(float a, float b) {
    return (unsigned)bfbits(a) | ((unsigned)bfbits(b) << 16);
}
__device__ __forceinline__ float resid(float w) { return w - bf2f(bfbits(w)); }
__device__ __forceinline__ float sigf(float x) {
    return __fdividef(1.0f, 1.0f + __expf(-x));
}
__device__ __forceinline__ float tanh_(float x) {
    return __fdividef(2.0f, 1.0f + __expf(-2.0f * x)) - 1.0f;
}
__device__ __forceinline__ void mma16816(float (&d)[4], const uint4 a,
                                         unsigned b0, unsigned b1) {
    asm volatile(
        "mma.sync.aligned.m16n8k16.row.col.f32.bf16.bf16.f32 "
        "{%0,%1,%2,%3},{%4,%5,%6,%7},{%8,%9},{%0,%1,%2,%3};"
        : "+f"(d[0]), "+f"(d[1]), "+f"(d[2]), "+f"(d[3])
        : "r"(a.x), "r"(a.y), "r"(a.z), "r"(a.w), "r"(b0), "r"(b1));
}
__device__ __forceinline__ void grid_sync(unsigned gen) {
    __syncthreads();
    if (threadIdx.x == 0) {
        __threadfence();
        atomicAdd(&g_bar, 1u);
        while (*((volatile unsigned*)&g_bar) < gen * NCTA) { }
        __threadfence();
    }
    __syncthreads();
}

// GEMM slice: 3 gates x 2 n8 x CNT kg; 3 rounds of 6 independent MMAs.
template<int KT, int CNT>
__device__ __forceinline__ void mloop(
    const uint4* __restrict__ fA,   // + jt*3*KT*64 + lane
    const uint4* __restrict__ bx,   // + boff
    int kgs,
    float (&aR)[2][4], float (&aZ)[2][4], float (&aN)[2][4])
{
    const uint4* a0 = fA + (size_t)kgs * 64;
    const uint4* bp = bx + (size_t)kgs * 256;
#pragma unroll 2
    for (int k = 0; k < CNT; ++k) {
        uint4 A0h = a0[0],           A0l = a0[32];
        uint4 A1h = a0[KT * 64],     A1l = a0[KT * 64 + 32];
        uint4 A2h = a0[2 * KT * 64], A2l = a0[2 * KT * 64 + 32];
        uint4 v0 = bp[0], v1 = bp[32];
        mma16816(aR[0], A0h, v0.x, v0.y); mma16816(aR[1], A0h, v1.x, v1.y);
        mma16816(aZ[0], A1h, v0.x, v0.y); mma16816(aZ[1], A1h, v1.x, v1.y);
        mma16816(aN[0], A2h, v0.x, v0.y); mma16816(aN[1], A2h, v1.x, v1.y);
        mma16816(aR[0], A0h, v0.z, v0.w); mma16816(aR[1], A0h, v1.z, v1.w);
        mma16816(aZ[0], A1h, v0.z, v0.w); mma16816(aZ[1], A1h, v1.z, v1.w);
        mma16816(aN[0], A2h, v0.z, v0.w); mma16816(aN[1], A2h, v1.z, v1.w);
        mma16816(aR[0], A0l, v0.x, v0.y); mma16816(aR[1], A0l, v1.x, v1.y);
        mma16816(aZ[0], A1l, v0.x, v0.y); mma16816(aZ[1], A1l, v1.x, v1.y);
        mma16816(aN[0], A2l, v0.x, v0.y); mma16816(aN[1], A2l, v1.x, v1.y);
        a0 += 64; bp += 256;
    }
}

// 4-way ksub reduce via SMEM + publish [q4][jl16][b32].
__device__ __forceinline__ void reduce_pub(
    float (&fR)[2][4], float (&fZ)[2][4], float (&fNi)[2][4], float (&fNh)[2][4],
    float* __restrict__ pOut, float* rbuf, int nsub, int ksub, int lane)
{
    if (ksub) {
        float* dst = rbuf + ((ksub - 1) * 2 + nsub) * 1024 + lane;
#pragma unroll
        for (int p = 0; p < 2; ++p)
#pragma unroll
            for (int e = 0; e < 4; ++e) {
                dst[(0  + p * 4 + e) * 32] = fR[p][e];
                dst[(8  + p * 4 + e) * 32] = fZ[p][e];
                dst[(16 + p * 4 + e) * 32] = fNi[p][e];
                dst[(24 + p * 4 + e) * 32] = fNh[p][e];
            }
    }
    __syncthreads();
    if (ksub == 0) {
#pragma unroll
        for (int q = 0; q < 4; ++q)
#pragma unroll
            for (int p = 0; p < 2; ++p)
#pragma unroll
                for (int e = 0; e < 4; ++e) {
                    float v = (q == 0 ? fR[p][e] : q == 1 ? fZ[p][e]
                             : q == 2 ? fNi[p][e] : fNh[p][e]);
                    const int idx = q * 8 + p * 4 + e;
#pragma unroll
                    for (int w = 0; w < 3; ++w)
                        v += rbuf[(w * 2 + nsub) * 1024 + idx * 32 + lane];
                    int jl = (lane >> 2) + 8 * (e >> 1);
                    int bl = nsub * 16 + p * 8 + 2 * (lane & 3) + (e & 1);
                    pOut[q * 512 + jl * 32 + bl] = v;
                }
    }
    __syncthreads();
}

__global__ void __launch_bounds__(NT, 2) gru_occ(
    const float* __restrict__ x,
    const float* __restrict__ Wi0, const float* __restrict__ Wh0,
    const float* __restrict__ bi0, const float* __restrict__ bh0,
    const float* __restrict__ Wi1, const float* __restrict__ Wh1,
    const float* __restrict__ bi1, const float* __restrict__ bh1,
    const float* __restrict__ Wo,  const float* __restrict__ bo,
    float* __restrict__ out)
{
    __shared__ float rbuf[3 * 2 * 32 * 32];   // 24 KB

    const int tid  = threadIdx.x, lane = tid & 31, warp = tid >> 5;
    const int cta  = blockIdx.x;
    const int jt   = cta >> 2;       // j-tile (16 h-units)
    const int ks   = (cta >> 1) & 1; // k-half
    const int bs   = cta & 1;        // batch half (32)
    const int nsub = warp & 1;       // batch quarter within half (16)
    const int ksub = warp >> 1;      // k-quarter of the CTA's k-half

    // ---- prep: x -> fragment-ordered split-bf16 (R10-verified format) ----
    {
        unsigned* xw = (unsigned*)g_xx;
        const int XW = T_ * KT0 * B_ * 16;
        for (int w = cta * NT + tid; w < XW; w += NCTA * NT) {
            int wi = w & 3, qq = (w >> 2) & 3, b = (w >> 4) & 63;
            int kg = (w >> 10) & 15, t = w >> 14;
            int pw = (wi & 1) ? qq + 4 : qq;
            int k  = kg * 16 + pw * 2;
            float v0 = x[((size_t)b * T_ + t) * DIN + k];
            float v1 = x[((size_t)b * T_ + t) * DIN + k + 1];
            xw[w] = (wi < 2) ? pk(v0, v1) : pk(resid(v0), resid(v1));
        }
    }
    // ---- zero initial state (buffer 1 read first) ----
    {
        unsigned* z0 = (unsigned*)g_h0x[1];
        unsigned* z1 = (unsigned*)g_h1x[1];
        for (int i = cta * NT + tid; i < KTH * B_ * 16; i += NCTA * NT) {
            z0[i] = 0u; z1[i] = 0u;
        }
        for (int i = cta * NT + tid; i < B_ * H_; i += NCTA * NT) {
            g_h0f[1][i] = 0.f; g_h1f[1][i] = 0.f;
        }
    }
    // ---- weights -> fragment-direct split-bf16 table (R5-verified) ----
    {
        const float* Wp[4] = { Wi0, Wh0, Wi1, Wh1 };
        const int    Kp[4] = { DIN, H_, H_, H_ };
        const size_t Fp[4] = { FB0, FB1, FB2, FB3 };
        for (int p = 0; p < 4; ++p) {
            const int K = Kp[p], KT = K / 16;
            const float* W = Wp[p];
            const int total = 64 * 3 * KT * 32;
            for (int i = cta * NT + tid; i < total; i += NCTA * NT) {
                int l = i & 31, item = i >> 5;
                int kg = item % KT, g = (item / KT) % 3, jtt = item / (KT * 3);
                int m = l >> 2, kb = 2 * (l & 3);
                const float* r0 = W + (size_t)(g * H_ + jtt * 16 + m) * K + kg * 16 + kb;
                const float* r1 = r0 + 8 * (size_t)K;
                float w00 = r0[0], w01 = r0[1], w02 = r0[8], w03 = r0[9];
                float w10 = r1[0], w11 = r1[1], w12 = r1[8], w13 = r1[9];
                uint4 hv, lv;
                hv.x = pk(w00, w01); hv.y = pk(w10, w11);
                hv.z = pk(w02, w03); hv.w = pk(w12, w13);
                lv.x = pk(resid(w00), resid(w01)); lv.y = pk(resid(w10), resid(w11));
                lv.z = pk(resid(w02), resid(w03)); lv.w = pk(resid(w12), resid(w13));
                size_t base = Fp[p] + ((size_t)(jtt * 3 + g) * KT + kg) * 64;
                g_wA[base + l] = hv;
                g_wA[base + 32 + l] = lv;
            }
        }
    }
    // ---- gate-pass biases: thread gates ONE (j, b) ----
    const int gj  = jt * 16 + 8 * ks + (tid >> 5);   // h-unit this thread gates
    const int gb  = bs * 32 + (tid & 31);            // global batch row
    float bs0v[4], bs1v[4];
    bs0v[0] = bi0[gj] + bh0[gj];
    bs0v[1] = bi0[H_ + gj] + bh0[H_ + gj];
    bs0v[2] = bi0[2 * H_ + gj];
    bs0v[3] = bh0[2 * H_ + gj];
    bs1v[0] = bi1[gj] + bh1[gj];
    bs1v[1] = bi1[H_ + gj] + bh1[H_ + gj];
    bs1v[2] = bi1[2 * H_ + gj];
    bs1v[3] = bh1[2 * H_ + gj];

    const uint4* fWi0 = g_wA + FB0 + (size_t)jt * 3 * KT0 * 64 + lane;
    const uint4* fWh0 = g_wA + FB1 + (size_t)jt * 3 * KTH * 64 + lane;
    const uint4* fWi1 = g_wA + FB2 + (size_t)jt * 3 * KTH * 64 + lane;
    const uint4* fWh1 = g_wA + FB3 + (size_t)jt * 3 * KTH * 64 + lane;
    const unsigned boff = (unsigned)((bs * 32 + nsub * 16) * 4
                                     + (lane >> 2) * 4 + (lane & 3));
    const int kgs0 = ks * 8  + ksub * 2;   // x GEMM: 2 kg per warp
    const int kgsH = ks * 32 + ksub * 8;   // h GEMMs: 8 kg per warp

    float* pOwn0 = g_p0 + (size_t)cta * 2048;
    float* pOwn1 = g_p1 + (size_t)cta * 2048;
    const float* pPar0 = g_p0 + (size_t)(cta ^ 2) * 2048;
    const float* pPar1 = g_p1 + (size_t)(cta ^ 2) * 2048;
    const int go = (8 * ks + (tid >> 5)) * 32 + (tid & 31);  // own partial idx

    unsigned gen = 0;
    grid_sync(++gen);   // prep visible

    for (int p = 0; p <= T_; ++p) {
        const int rb0 = (p + 1) & 1;
        // ---- layer0(t=p) partial ----
        if (p < T_) {
            float aR[2][4] = {}, aZ[2][4] = {}, aNi[2][4] = {}, aNh[2][4] = {};
            mloop<KT0, 2>(fWi0, g_xx + (size_t)p * 4096 + boff, kgs0, aR, aZ, aNi);
            mloop<KTH, 8>(fWh0, g_h0x[rb0] + boff, kgsH, aR, aZ, aNh);
            reduce_pub(aR, aZ, aNi, aNh, pOwn0, rbuf, nsub, ksub, lane);
        }
        __syncthreads();
        if (tid == 0 && p < T_) { __threadfence(); g_f0[cta] = p + 1; }
        // ---- layer1(t=p-1) partial ----
        if (p > 0) {
            float aR[2][4] = {}, aZ[2][4] = {}, aNi[2][4] = {}, aNh[2][4] = {};
            mloop<KTH, 8>(fWi1, g_h0x[rb0] + boff, kgsH, aR, aZ, aNi);
            mloop<KTH, 8>(fWh1, g_h1x[p & 1] + boff, kgsH, aR, aZ, aNh);
            reduce_pub(aR, aZ, aNi, aNh, pOwn1, rbuf, nsub, ksub, lane);
        }
        __syncthreads();
        if (tid == 0) {
            if (p > 0) { __threadfence(); g_f1[cta] = p; }
            if (p < T_) while (g_f0[cta ^ 2] < (unsigned)(p + 1)) { }
            if (p > 0)  while (g_f1[cta ^ 2] < (unsigned)p) { }
            __threadfence();
        }
        __syncthreads();
        // ---- gate passes: one (j, b) per thread ----
        if (p < T_) {
            float r  = sigf(pOwn0[go] + pPar0[go] + bs0v[0]);
            float z  = sigf(pOwn0[512 + go] + pPar0[512 + go] + bs0v[1]);
            float ni = pOwn0[1024 + go] + pPar0[1024 + go] + bs0v[2];
            float nh = pOwn0[1536 + go] + pPar0[1536 + go] + bs0v[3];
            float n  = tanh_(ni + r * nh);
            float hp = g_h0f[rb0][gb * H_ + gj];
            float h  = n + z * (hp - n);
            g_h0f[p & 1][gb * H_ + gj] = h;
            unsigned short uh = bfbits(h);
            unsigned short ul = bfbits(h - bf2f(uh));
            int kg = gj >> 4, pw = (gj & 15) >> 1, qq = pw & 3, sl = pw >> 2;
            char* base = (char*)(g_h0x[p & 1] + (size_t)(kg * 64 + gb) * 4 + qq);
            *(unsigned short*)(base + sl * 4 + (gj & 1) * 2)     = uh;
            *(unsigned short*)(base + 8 + sl * 4 + (gj & 1) * 2) = ul;
        }
        if (p > 0) {
            float r  = sigf(pOwn1[go] + pPar1[go] + bs1v[0]);
            float z  = sigf(pOwn1[512 + go] + pPar1[512 + go] + bs1v[1]);
            float ni = pOwn1[1024 + go] + pPar1[1024 + go] + bs1v[2];
            float nh = pOwn1[1536 + go] + pPar1[1536 + go] + bs1v[3];
            float n  = tanh_(ni + r * nh);
            float hp = g_h1f[p & 1][gb * H_ + gj];
            float h  = n + z * (hp - n);
            g_h1f[(p + 1) & 1][gb * H_ + gj] = h;
            unsigned short uh = bfbits(h);
            unsigned short ul = bfbits(h - bf2f(uh));
            int kg = gj >> 4, pw = (gj & 15) >> 1, qq = pw & 3, sl = pw >> 2;
            char* base = (char*)(g_h1x[(p + 1) & 1] + (size_t)(kg * 64 + gb) * 4 + qq);
            *(unsigned short*)(base + sl * 4 + (gj & 1) * 2)     = uh;
            *(unsigned short*)(base + 8 + sl * 4 + (gj & 1) * 2) = ul;
        }
        grid_sync(++gen);
    }

    // ---- output projection: CTA = output column o; h1(511) in g_h1f[1] ----
    {
        const int o = cta, b = tid & 63, seg = tid >> 6;
        const float* w  = Wo + (size_t)o * H_ + seg * 256;
        const float* hv = g_h1f[1] + (size_t)b * H_ + seg * 256;
        float acc = 0.f;
#pragma unroll 4
        for (int k = 0; k < 256; k += 4) {
            float4 wv = *(const float4*)(w + k);
            float4 h4 = *(const float4*)(hv + k);
            acc += wv.x * h4.x + wv.y * h4.y + wv.z * h4.z + wv.w * h4.w;
        }
        rbuf[tid] = acc;
        __syncthreads();
        if (tid < 64)
            out[(size_t)b * DOUT + o] =
                rbuf[b] + rbuf[64 + b] + rbuf[128 + b] + rbuf[192 + b] + bo[o];
    }

    // ---- reset persistent counters for next replay ----
    __syncthreads();
    if (tid == 0) {
        unsigned old = atomicAdd(&g_done, 1u);
        if (old == NCTA - 1u) {
            for (int i = 0; i < NCTA; ++i) { g_f0[i] = 0u; g_f1[i] = 0u; }
            g_bar = 0u;
            g_done = 0u;
            __threadfence();
        }
    }
}

extern "C" void kernel_launch(void* const* d_in, const int* in_sizes, int n_in,
                              void* d_out, int out_size)
{
    gru_occ<<<NCTA, NT>>>(
        (const float*)d_in[0], (const float*)d_in[1], (const float*)d_in[2],
        (const float*)d_in[3], (const float*)d_in[4], (const float*)d_in[5],
        (const float*)d_in[6], (const float*)d_in[7], (const float*)d_in[8],
        (const float*)d_in[9], (const float*)d_in[10], (float*)d_out);
}

// round 14
// speedup vs baseline: 2.8656x; 1.4692x over previous
#include <cuda_runtime.h>
#include <cuda_fp16.h>

#define B_   64
#define T_   512
#define DIN  256
#define H_   1024
#define DOUT 256
#define NCTA 128
#define NT   256

constexpr int KT0 = 16;
constexpr int KTH = 64;
constexpr size_t FSZ0 = (size_t)64 * 3 * KT0 * 64;
constexpr size_t FSZH = (size_t)64 * 3 * KTH * 64;
constexpr size_t FB0 = 0, FB1 = FSZ0, FB2 = FSZ0 + FSZH, FB3 = FSZ0 + 2 * FSZH;

__device__ uint4 g_wA[FSZ0 + 3 * FSZH];            // fp16 frag table (hi, lo)
__device__ float g_h0f[2][B_ * H_], g_h1f[2][B_ * H_];
__device__ unsigned g_h0x[2][KTH * B_ * 8];        // fp16 act frags [kg][b][qq][sel]
__device__ unsigned g_h1x[2][KTH * B_ * 8];
__device__ unsigned g_xx[(size_t)T_ * KT0 * B_ * 8];
__device__ float g_pL0[NCTA * 4096], g_pL1[NCTA * 4096];
__device__ volatile unsigned g_fL0[NCTA], g_fL1[NCTA];
__device__ unsigned g_bar, g_done;

__device__ __forceinline__ unsigned short hfb(float v) {
    __half h = __float2half_rn(v);
    return *reinterpret_cast<unsigned short*>(&h);
}
__device__ __forceinline__ float h2f(unsigned short u) {
    __half h = *reinterpret_cast<__half*>(&u);
    return __half2float(h);
}
__device__ __forceinline__ unsigned pk(float a, float b) {
    return (unsigned)hfb(a) | ((unsigned)hfb(b) << 16);
}
__device__ __forceinline__ float resid(float w) { return w - h2f(hfb(w)); }
__device__ __forceinline__ float sigf(float x) {
    return __fdividef(1.0f, 1.0f + __expf(-x));
}
__device__ __forceinline__ float tanh_(float x) {
    return __fdividef(2.0f, 1.0f + __expf(-2.0f * x)) - 1.0f;
}
__device__ __forceinline__ void mmaf16(float (&d)[4], const uint4 a,
                                       unsigned b0, unsigned b1) {
    asm volatile(
        "mma.sync.aligned.m16n8k16.row.col.f32.f16.f16.f32 "
        "{%0,%1,%2,%3},{%4,%5,%6,%7},{%8,%9},{%0,%1,%2,%3};"
        : "+f"(d[0]), "+f"(d[1]), "+f"(d[2]), "+f"(d[3])
        : "r"(a.x), "r"(a.y), "r"(a.z), "r"(a.w), "r"(b0), "r"(b1));
}
__device__ __forceinline__ void grid_sync(unsigned gen) {
    __syncthreads();
    if (threadIdx.x == 0) {
        __threadfence();
        atomicAdd(&g_bar, 1u);
        while (*((volatile unsigned*)&g_bar) < gen * NCTA) { }
        __threadfence();
    }
    __syncthreads();
}

// GEMM slice: 4 MMAs per (kg, n8): r/z/n hi + n lo (subnormal, shared accum).
template<int KT, int CNT>
__device__ __forceinline__ void mloop(
    const uint4* __restrict__ fA,       // + jt*3*KT*64 + lane
    const unsigned* __restrict__ bx,    // act words + boff
    int kgs,
    float (&aR)[4][4], float (&aZ)[4][4], float (&aN)[4][4])
{
    const uint4* a0 = fA + (size_t)kgs * 64;
    const uint2* bp = reinterpret_cast<const uint2*>(bx) + (size_t)kgs * 256;
#pragma unroll 4
    for (int k = 0; k < CNT; ++k) {
        uint4 A0h = a0[0];
        uint4 A1h = a0[KT * 64];
        uint4 A2h = a0[2 * KT * 64];
        uint4 A2l = a0[2 * KT * 64 + 32];
        uint2 v[4];
#pragma unroll
        for (int i = 0; i < 4; ++i) v[i] = bp[i * 32];
#pragma unroll
        for (int i = 0; i < 4; ++i) mmaf16(aR[i], A0h, v[i].x, v[i].y);
#pragma unroll
        for (int i = 0; i < 4; ++i) mmaf16(aZ[i], A1h, v[i].x, v[i].y);
#pragma unroll
        for (int i = 0; i < 4; ++i) mmaf16(aN[i], A2h, v[i].x, v[i].y);
#pragma unroll
        for (int i = 0; i < 4; ++i) mmaf16(aN[i], A2l, v[i].x, v[i].y);
        a0 += 64; bp += 256;
    }
}

// ksub-reduce via SMEM + publish CTA partial [qty4][j16][b64] (R10-verified).
#define REDUCE_PUBLISH(AR, AZ, ANI, ANH, POUT)                                 \
    do {                                                                       \
        if (ksub) {                                                           \
            float* dst = rbuf + (((ksub - 1) * 2 + nsub) * 64) * 32 + lane;   \
            _Pragma("unroll")                                                 \
            for (int i = 0; i < 16; ++i) {                                    \
                dst[(0 * 16 + i) * 32] = AR[i >> 2][i & 3];                   \
                dst[(1 * 16 + i) * 32] = AZ[i >> 2][i & 3];                   \
                dst[(2 * 16 + i) * 32] = ANI[i >> 2][i & 3];                  \
                dst[(3 * 16 + i) * 32] = ANH[i >> 2][i & 3];                  \
            }                                                                 \
        }                                                                     \
        __syncthreads();                                                      \
        if (ksub == 0) {                                                      \
            _Pragma("unroll")                                                 \
            for (int q = 0; q < 4; ++q) {                                     \
                _Pragma("unroll")                                             \
                for (int i = 0; i < 16; ++i) {                                \
                    float v = (q == 0 ? AR[i >> 2][i & 3]                     \
                             : q == 1 ? AZ[i >> 2][i & 3]                     \
                             : q == 2 ? ANI[i >> 2][i & 3]                    \
                                      : ANH[i >> 2][i & 3]);                  \
                    _Pragma("unroll")                                         \
                    for (int w = 0; w < 3; ++w)                               \
                        v += rbuf[((w * 2 + nsub) * 64 + q * 16 + i) * 32 + lane]; \
                    int jl = (lane >> 2) + 8 * ((i & 3) >> 1);                \
                    int b  = nsub * 32 + (i >> 2) * 8 + 2 * (lane & 3) + (i & 1); \
                    (POUT)[q * 1024 + jl * 64 + b] = v;                       \
                }                                                             \
            }                                                                 \
        }                                                                     \
        __syncthreads();                                                      \
    } while (0)

__device__ __forceinline__ void gatepass(
    const float* __restrict__ pOwn, const float* __restrict__ pPar,
    const float* bsv,
    const float* __restrict__ hpf, float* __restrict__ hnf,
    unsigned* __restrict__ hw,
    int jt, int ks, int tid)
{
    const int b = tid & 63, jl2 = tid >> 6;
#pragma unroll
    for (int jj = 0; jj < 2; ++jj) {
        int jl = 8 * ks + jl2 * 2 + jj;
        int j  = jt * 16 + jl;
        int o  = jl * 64 + b;
        float r  = pOwn[o]        + pPar[o];
        float z  = pOwn[1024 + o] + pPar[1024 + o];
        float ni = pOwn[2048 + o] + pPar[2048 + o];
        float nh = pOwn[3072 + o] + pPar[3072 + o];
        r = sigf(r + bsv[jj * 4 + 0]);
        z = sigf(z + bsv[jj * 4 + 1]);
        float n = tanh_(ni + bsv[jj * 4 + 2] + r * (nh + bsv[jj * 4 + 3]));
        float hp = hpf[b * H_ + j];
        float h  = n + z * (hp - n);
        hnf[b * H_ + j] = h;
        int kg = j >> 4, pw = (j & 15) >> 1, qq = pw & 3, sl = pw >> 2;
        unsigned idx = (unsigned)(((kg * 64 + b) * 4 + qq) * 2 + sl);
        reinterpret_cast<unsigned short*>(hw + idx)[j & 1] = hfb(h);
    }
}

__global__ void __launch_bounds__(NT, 1) gru_f16(
    const float* __restrict__ x,
    const float* __restrict__ Wi0, const float* __restrict__ Wh0,
    const float* __restrict__ bi0, const float* __restrict__ bh0,
    const float* __restrict__ Wi1, const float* __restrict__ Wh1,
    const float* __restrict__ bi1, const float* __restrict__ bh1,
    const float* __restrict__ Wo,  const float* __restrict__ bo,
    float* __restrict__ out)
{
    __shared__ float rbuf[3 * 2 * 64 * 32];   // 48 KB reduce buffer

    const int tid  = threadIdx.x, lane = tid & 31, warp = tid >> 5;
    const int cta  = blockIdx.x;
    const int jt   = cta >> 1;       // j-tile (16 gate rows per gate)
    const int ks   = cta & 1;        // k-half
    const int nsub = warp & 1;       // batch half (32)
    const int ksub = warp >> 1;      // k-quarter of the half

    // ---- prep: x -> single-fp16 fragment words ----
    {
        const int XW = T_ * KT0 * B_ * 8;
        for (int w = cta * NT + tid; w < XW; w += NCTA * NT) {
            int sel = w & 1, qq = (w >> 1) & 3, b = (w >> 3) & 63;
            int kg = (w >> 9) & 15, t = w >> 13;
            int k0 = kg * 16 + qq * 2 + sel * 8;
            g_xx[w] = pk(x[((size_t)b * T_ + t) * DIN + k0],
                         x[((size_t)b * T_ + t) * DIN + k0 + 1]);
        }
    }
    // ---- zero initial state (buffer 1 read first) ----
    for (int i = cta * NT + tid; i < KTH * B_ * 8; i += NCTA * NT) {
        g_h0x[1][i] = 0u; g_h1x[1][i] = 0u;
    }
    for (int i = cta * NT + tid; i < B_ * H_; i += NCTA * NT) {
        g_h0f[1][i] = 0.f; g_h1f[1][i] = 0.f;
    }
    // ---- weights -> fp16 hi/lo fragment table (R5 layout, fp16 values) ----
    {
        const float* Wp[4] = { Wi0, Wh0, Wi1, Wh1 };
        const int    Kp[4] = { DIN, H_, H_, H_ };
        const size_t Fp[4] = { FB0, FB1, FB2, FB3 };
        for (int p = 0; p < 4; ++p) {
            const int K = Kp[p], KT = K / 16;
            const float* W = Wp[p];
            const int total = 64 * 3 * KT * 32;
            for (int i = cta * NT + tid; i < total; i += NCTA * NT) {
                int l = i & 31, item = i >> 5;
                int kg = item % KT, g = (item / KT) % 3, jtt = item / (KT * 3);
                int m = l >> 2, kb = 2 * (l & 3);
                const float* r0 = W + (size_t)(g * H_ + jtt * 16 + m) * K + kg * 16 + kb;
                const float* r1 = r0 + 8 * (size_t)K;
                float w00 = r0[0], w01 = r0[1], w02 = r0[8], w03 = r0[9];
                float w10 = r1[0], w11 = r1[1], w12 = r1[8], w13 = r1[9];
                uint4 hv, lv;
                hv.x = pk(w00, w01); hv.y = pk(w10, w11);
                hv.z = pk(w02, w03); hv.w = pk(w12, w13);
                lv.x = pk(resid(w00), resid(w01)); lv.y = pk(resid(w10), resid(w11));
                lv.z = pk(resid(w02), resid(w03)); lv.w = pk(resid(w12), resid(w13));
                size_t base = Fp[p] + ((size_t)(jtt * 3 + g) * KT + kg) * 64;
                g_wA[base + l] = hv;
                g_wA[base + 32 + l] = lv;
            }
        }
    }
    // ---- gate-pass biases ----
    float bs0v[8], bs1v[8];
    {
        const int jl2 = tid >> 6;
#pragma unroll
        for (int jj = 0; jj < 2; ++jj) {
            int j = jt * 16 + 8 * ks + jl2 * 2 + jj;
            bs0v[jj * 4 + 0] = bi0[j] + bh0[j];
            bs0v[jj * 4 + 1] = bi0[H_ + j] + bh0[H_ + j];
            bs0v[jj * 4 + 2] = bi0[2 * H_ + j];
            bs0v[jj * 4 + 3] = bh0[2 * H_ + j];
            bs1v[jj * 4 + 0] = bi1[j] + bh1[j];
            bs1v[jj * 4 + 1] = bi1[H_ + j] + bh1[H_ + j];
            bs1v[jj * 4 + 2] = bi1[2 * H_ + j];
            bs1v[jj * 4 + 3] = bh1[2 * H_ + j];
        }
    }

    const uint4* fWi0 = g_wA + FB0 + (size_t)jt * 3 * KT0 * 64 + lane;
    const uint4* fWh0 = g_wA + FB1 + (size_t)jt * 3 * KTH * 64 + lane;
    const uint4* fWi1 = g_wA + FB2 + (size_t)jt * 3 * KTH * 64 + lane;
    const uint4* fWh1 = g_wA + FB3 + (size_t)jt * 3 * KTH * 64 + lane;
    const unsigned boff = (unsigned)(nsub * 256 + ((lane >> 2) * 4 + (lane & 3)) * 2);
    const int kgs0 = ks * 8  + ksub * 2;   // x GEMM: 2 kg per warp
    const int kgsH = ks * 32 + ksub * 8;   // h GEMMs: 8 kg per warp

    float* pOwn0 = g_pL0 + cta * 4096;
    float* pOwn1 = g_pL1 + cta * 4096;
    const float* pPar0 = g_pL0 + (cta ^ 1) * 4096;
    const float* pPar1 = g_pL1 + (cta ^ 1) * 4096;

    unsigned gen = 0;
    grid_sync(++gen);   // prep visible

    for (int p = 0; p <= T_; ++p) {
        const int rb0 = (p + 1) & 1;
        // ---- layer0(t=p) partial ----
        if (p < T_) {
            float aR[4][4] = {}, aZ[4][4] = {}, aNi[4][4] = {}, aNh[4][4] = {};
            mloop<KT0, 2>(fWi0, g_xx + (size_t)p * 8192 + boff, kgs0, aR, aZ, aNi);
            mloop<KTH, 8>(fWh0, g_h0x[rb0] + boff, kgsH, aR, aZ, aNh);
            REDUCE_PUBLISH(aR, aZ, aNi, aNh, pOwn0);
        }
        __syncthreads();
        if (tid == 0 && p < T_) { __threadfence(); g_fL0[cta] = p + 1; }
        // ---- layer1(t=p-1) partial ----
        if (p > 0) {
            float aR[4][4] = {}, aZ[4][4] = {}, aNi[4][4] = {}, aNh[4][4] = {};
            mloop<KTH, 8>(fWi1, g_h0x[rb0] + boff, kgsH, aR, aZ, aNi);
            mloop<KTH, 8>(fWh1, g_h1x[p & 1] + boff, kgsH, aR, aZ, aNh);
            REDUCE_PUBLISH(aR, aZ, aNi, aNh, pOwn1);
        }
        __syncthreads();
        if (tid == 0) {
            if (p > 0) { __threadfence(); g_fL1[cta] = p; }
            if (p < T_) while (g_fL0[cta ^ 1] < (unsigned)(p + 1)) { }
            if (p > 0)  while (g_fL1[cta ^ 1] < (unsigned)p) { }
            __threadfence();
        }
        __syncthreads();
        // ---- gate passes ----
        if (p < T_)
            gatepass(pOwn0, pPar0, bs0v, g_h0f[rb0], g_h0f[p & 1],
                     g_h0x[p & 1], jt, ks, tid);
        if (p > 0)
            gatepass(pOwn1, pPar1, bs1v, g_h1f[p & 1], g_h1f[(p + 1) & 1],
                     g_h1x[(p + 1) & 1], jt, ks, tid);
        grid_sync(++gen);
    }

    // ---- output projection: h1(511) in g_h1f[1] ----
    if (tid < 128) {
        const int o = cta * 2 + (tid >> 6);
        const int b = tid & 63;
        const float* w  = Wo + (size_t)o * H_;
        const float* hv = g_h1f[1] + (size_t)b * H_;
        float acc = 0.f;
#pragma unroll 4
        for (int k = 0; k < H_; k += 4) {
            float4 wv = *(const float4*)(w + k);
            float4 h4 = *(const float4*)(hv + k);
            acc += wv.x * h4.x + wv.y * h4.y + wv.z * h4.z + wv.w * h4.w;
        }
        out[(size_t)b * DOUT + o] = acc + bo[o];
    }

    // ---- reset persistent counters for next replay ----
    __syncthreads();
    if (tid == 0) {
        unsigned old = atomicAdd(&g_done, 1u);
        if (old == NCTA - 1u) {
            for (int i = 0; i < NCTA; ++i) { g_fL0[i] = 0u; g_fL1[i] = 0u; }
            g_bar = 0u;
            g_done = 0u;
            __threadfence();
        }
    }
}

extern "C" void kernel_launch(void* const* d_in, const int* in_sizes, int n_in,
                              void* d_out, int out_size)
{
    gru_f16<<<NCTA, NT>>>(
        (const float*)d_in[0], (const float*)d_in[1], (const float*)d_in[2],
        (const float*)d_in[3], (const float*)d_in[4], (const float*)d_in[5],
        (const float*)d_in[6], (const float*)d_in[7], (const float*)d_in[8],
        (const float*)d_in[9], (const float*)d_in[10], (float*)d_out);
}